// round 9
// baseline (speedup 1.0000x reference)
#include <cuda_runtime.h>

#define N_NODES 50000
#define MAX_E   900000

// Scratch (device globals — no allocation allowed)
__device__ float g_h0[N_NODES * 128];
__device__ float g_h [N_NODES * 128];
__device__ float g_h2[N_NODES * 64];
__device__ int   g_cnt_in[N_NODES];
__device__ int   g_cnt_out[N_NODES];
__device__ int   g_off_in[N_NODES];
__device__ int   g_off_out[N_NODES];
__device__ int   g_cur_in[N_NODES];
__device__ int   g_cur_out[N_NODES];
__device__ int   g_csr_in[MAX_E];
__device__ int   g_csr_out[MAX_E];
__device__ int   g_base_in;
__device__ int   g_base_out;

typedef unsigned long long u64;

__device__ __forceinline__ u64 pack2(float lo, float hi) {
    u64 r; asm("mov.b64 %0, {%1, %2};" : "=l"(r) : "f"(lo), "f"(hi)); return r;
}
__device__ __forceinline__ void unpack2(u64 v, float& lo, float& hi) {
    asm("mov.b64 {%0, %1}, %2;" : "=f"(lo), "=f"(hi) : "l"(v));
}
__device__ __forceinline__ void fma2(u64& acc, u64 a, u64 b) {
    asm("fma.rn.f32x2 %0, %1, %2, %0;" : "+l"(acc) : "l"(a), "l"(b));
}

__global__ void zero_cnt_kernel(int n) {
    int i = blockIdx.x * blockDim.x + threadIdx.x;
    if (i < n) { g_cnt_in[i] = 0; g_cnt_out[i] = 0; }
    if (i == 0) { g_base_in = 0; g_base_out = 0; }
}

// 4 edges per thread: 8 independent atomic chains for latency hiding.
__global__ void degree_kernel(const int* __restrict__ ei, int E) {
    int i = blockIdx.x * blockDim.x + threadIdx.x;
    int base = i * 4;
    if (base + 3 < E) {
        int4 r = ((const int4*)ei)[i];
        int4 c = ((const int4*)(ei + E))[i];
        atomicAdd(&g_cnt_out[r.x], 1); atomicAdd(&g_cnt_out[r.y], 1);
        atomicAdd(&g_cnt_out[r.z], 1); atomicAdd(&g_cnt_out[r.w], 1);
        atomicAdd(&g_cnt_in[c.x], 1); atomicAdd(&g_cnt_in[c.y], 1);
        atomicAdd(&g_cnt_in[c.z], 1); atomicAdd(&g_cnt_in[c.w], 1);
    } else {
        for (int j = base; j < E; j++) {
            atomicAdd(&g_cnt_out[ei[j]], 1);
            atomicAdd(&g_cnt_in[ei[E + j]], 1);
        }
    }
}

// Block-local exclusive scan + atomic block base -> CSR segment starts.
__global__ void offsets_kernel(int n) {
    const int* cnt;
    int *off, *cur, *gbase;
    if (blockIdx.y == 0) { cnt = g_cnt_in;  off = g_off_in;  cur = g_cur_in;  gbase = &g_base_in; }
    else                 { cnt = g_cnt_out; off = g_off_out; cur = g_cur_out; gbase = &g_base_out; }

    __shared__ int wsum[32];
    __shared__ int sbase;
    int tid = threadIdx.x, lane = tid & 31, warp = tid >> 5;
    int v = blockIdx.x * blockDim.x + tid;
    int c = (v < n) ? cnt[v] : 0;
    int val = c;
#pragma unroll
    for (int d = 1; d < 32; d <<= 1) {
        int t = __shfl_up_sync(0xffffffffu, val, d);
        if (lane >= d) val += t;
    }
    if (lane == 31) wsum[warp] = val;
    __syncthreads();
    if (warp == 0) {
        int w = wsum[lane];
#pragma unroll
        for (int d = 1; d < 32; d <<= 1) {
            int t = __shfl_up_sync(0xffffffffu, w, d);
            if (lane >= d) w += t;
        }
        wsum[lane] = w;
    }
    __syncthreads();
    int incl = val + (warp ? wsum[warp - 1] : 0);
    if (tid == blockDim.x - 1) sbase = atomicAdd(gbase, incl);
    __syncthreads();
    if (v < n) {
        int o = sbase + incl - c;
        off[v] = o;
        cur[v] = o;
    }
}

__device__ __forceinline__ void fill_one(int r, int c) {
    int p = atomicAdd(&g_cur_in[c], 1);
    g_csr_in[p] = r;
    int q = atomicAdd(&g_cur_out[r], 1);
    g_csr_out[q] = c;
}

// ---------------------------------------------------------------------------
// f32x2 GEMM body. Y = X@W^T + B.  X:[n,128], W:[OUTC,128], B:[OUTC].
// 512 threads = 16 warps; warp = 4 rows (2 row-pairs); lane = OUTC/32 cols.
// smem: Wd[k][slot] = {w,w} duplicated pairs, swizzled so each lane's group
// read is one contiguous conflict-free LDS.128. Xs2[warp][k][p] = row-pair x.
// ---------------------------------------------------------------------------
template<int OUTC>
__device__ __forceinline__ void gemm_body(int bid,
                                          const float* __restrict__ X,
                                          const float* __restrict__ W,
                                          const float* __restrict__ B,
                                          float* __restrict__ Y,
                                          int n, u64* smU) {
    constexpr int INC = 128;
    constexpr int VEC = OUTC / 32;     // cols per lane
    constexpr int NG  = VEC / 2;       // LDS.128 groups per k (1 or 2)
    u64* Wd  = smU;                    // [128][OUTC] u64
    u64* Xs2 = smU + 128 * OUTC;       // [16 warps][128][2] u64

    int tid = threadIdx.x, lane = tid & 31, warp = tid >> 5;

    // W duplicated into smem: col j at k -> slot = g*64 + (j/VEC)*2 + (j&1)
    for (int i = tid; i < OUTC * INC; i += blockDim.x) {
        int j = i / INC, k = i - j * INC;
        float w = W[i];
        int slot = ((j % VEC) >> 1) * 64 + (j / VEC) * 2 + (j & 1);
        Wd[k * OUTC + slot] = pack2(w, w);
    }

    // X transpose into row-pair-interleaved layout
    int rowBase = bid * 64 + warp * 4;
    float* XsF = (float*)(Xs2 + warp * 256);
#pragma unroll
    for (int rr = 0; rr < 4; rr++) {
        int row = rowBase + rr;
        float4 v = make_float4(0.f, 0.f, 0.f, 0.f);
        if (row < n) v = ((const float4*)(X + (size_t)row * INC))[lane];
        int k0 = lane * 4;
        int pi = rr >> 1, hi = rr & 1;
        XsF[((k0 + 0) * 2 + pi) * 2 + hi] = v.x;
        XsF[((k0 + 1) * 2 + pi) * 2 + hi] = v.y;
        XsF[((k0 + 2) * 2 + pi) * 2 + hi] = v.z;
        XsF[((k0 + 3) * 2 + pi) * 2 + hi] = v.w;
    }
    __syncthreads();

    u64 acc[2][VEC];
#pragma unroll
    for (int v = 0; v < VEC; v++) {
        float b = B[lane * VEC + v];
        u64 bb = pack2(b, b);
        acc[0][v] = bb;
        acc[1][v] = bb;
    }

    const u64* wrow = Wd + lane * 2;
    const u64* xrow = Xs2 + warp * 256;
#pragma unroll 4
    for (int k = 0; k < INC; k++) {
        ulonglong2 xp = *(const ulonglong2*)(xrow + k * 2);   // {pair0, pair1}
#pragma unroll
        for (int g = 0; g < NG; g++) {
            ulonglong2 wg = *(const ulonglong2*)(wrow + k * OUTC + g * 64);
            fma2(acc[0][2 * g + 0], xp.x, wg.x);
            fma2(acc[0][2 * g + 1], xp.x, wg.y);
            fma2(acc[1][2 * g + 0], xp.y, wg.x);
            fma2(acc[1][2 * g + 1], xp.y, wg.y);
        }
    }

    float res[4][VEC];
#pragma unroll
    for (int p = 0; p < 2; p++)
#pragma unroll
        for (int v = 0; v < VEC; v++)
            unpack2(acc[p][v], res[2 * p][v], res[2 * p + 1][v]);

#pragma unroll
    for (int rr = 0; rr < 4; rr++) {
        int row = rowBase + rr;
        if (row < n) {
            if constexpr (VEC == 4) {
                float4 o = make_float4(res[rr][0], res[rr][1], res[rr][2], res[rr][3]);
                ((float4*)(Y + (size_t)row * OUTC))[lane] = o;
            } else {
                float2 o = make_float2(res[rr][0], res[rr][1]);
                ((float2*)(Y + (size_t)row * OUTC))[lane] = o;
            }
        }
    }
}

// Fused: blocks [0, fillBlocks) build both CSR adjacency arrays (latency-bound,
// hides under the compute-bound GEMM blocks); blocks [fillBlocks, ...) do GEMM128.
__global__ void fused_fill_gemm128(const int* __restrict__ ei, int E, int fillBlocks,
                                   const float* __restrict__ X,
                                   const float* __restrict__ W,
                                   const float* __restrict__ B,
                                   float* __restrict__ Y, int n) {
    extern __shared__ u64 smU[];
    if ((int)blockIdx.x < fillBlocks) {
        int i = blockIdx.x * blockDim.x + threadIdx.x;
        int base = i * 4;
        if (base + 3 < E) {
            int4 r = ((const int4*)ei)[i];
            int4 c = ((const int4*)(ei + E))[i];
            fill_one(r.x, c.x); fill_one(r.y, c.y);
            fill_one(r.z, c.z); fill_one(r.w, c.w);
        } else {
            for (int j = base; j < E; j++) fill_one(ei[j], ei[E + j]);
        }
    } else {
        gemm_body<128>(blockIdx.x - fillBlocks, X, W, B, Y, n, smU);
    }
}

__global__ void gemm64_kernel(const float* __restrict__ X,
                              const float* __restrict__ W,
                              const float* __restrict__ B,
                              float* __restrict__ Y, int n) {
    extern __shared__ u64 smU[];
    gemm_body<64>(blockIdx.x, X, W, B, Y, n, smU);
}

// CSR gather-aggregation, fused with normalization (and optional ReLU).
template<int C, bool RELU>
__global__ void agg_kernel(const float* __restrict__ src,
                           const int* __restrict__ off,
                           const int* __restrict__ cnt,
                           const int* __restrict__ csr,
                           float* __restrict__ dst, int n) {
    constexpr int LPE = C / 4;
    constexpr int NPW = 32 / LPE;
    int t = blockIdx.x * blockDim.x + threadIdx.x;
    int warp = t >> 5, lane = t & 31;
    int sub = lane / LPE, li = lane - sub * LPE;
    int v = warp * NPW + sub;
    if (v >= n) return;

    int beg = off[v];
    int deg = cnt[v];
    int end = beg + deg;

    float4 acc = ((const float4*)(src + (size_t)v * C))[li];  // self loop
    int e = beg;
    for (; e + 4 <= end; e += 4) {
        int s0 = csr[e], s1 = csr[e + 1], s2 = csr[e + 2], s3 = csr[e + 3];
        float4 a = ((const float4*)(src + (size_t)s0 * C))[li];
        float4 b = ((const float4*)(src + (size_t)s1 * C))[li];
        float4 c = ((const float4*)(src + (size_t)s2 * C))[li];
        float4 d = ((const float4*)(src + (size_t)s3 * C))[li];
        acc.x += (a.x + b.x) + (c.x + d.x);
        acc.y += (a.y + b.y) + (c.y + d.y);
        acc.z += (a.z + b.z) + (c.z + d.z);
        acc.w += (a.w + b.w) + (c.w + d.w);
    }
    for (; e < end; e++) {
        int s = csr[e];
        float4 a = ((const float4*)(src + (size_t)s * C))[li];
        acc.x += a.x; acc.y += a.y; acc.z += a.z; acc.w += a.w;
    }

    float inv = 1.0f / (float)(deg + 1);
    acc.x *= inv; acc.y *= inv; acc.z *= inv; acc.w *= inv;
    if (RELU) {
        acc.x = fmaxf(acc.x, 0.0f); acc.y = fmaxf(acc.y, 0.0f);
        acc.z = fmaxf(acc.z, 0.0f); acc.w = fmaxf(acc.w, 0.0f);
    }
    ((float4*)(dst + (size_t)v * C))[li] = acc;
}

extern "C" void kernel_launch(void* const* d_in, const int* in_sizes, int n_in,
                              void* d_out, int out_size) {
    const float* x  = (const float*)d_in[0];
    const int*   ei = (const int*)d_in[1];
    const float* W1 = (const float*)d_in[2];
    const float* b1 = (const float*)d_in[3];
    const float* W2 = (const float*)d_in[4];
    const float* b2 = (const float*)d_in[5];
    float* out = (float*)d_out;

    int n = in_sizes[0] / 128;
    int E = in_sizes[1] / 2;

    float *h0, *h, *h2;
    int *cnt_in, *cnt_out, *off_in, *off_out, *csr_in, *csr_out;
    cudaGetSymbolAddress((void**)&h0, g_h0);
    cudaGetSymbolAddress((void**)&h,  g_h);
    cudaGetSymbolAddress((void**)&h2, g_h2);
    cudaGetSymbolAddress((void**)&cnt_in,  g_cnt_in);
    cudaGetSymbolAddress((void**)&cnt_out, g_cnt_out);
    cudaGetSymbolAddress((void**)&off_in,  g_off_in);
    cudaGetSymbolAddress((void**)&off_out, g_off_out);
    cudaGetSymbolAddress((void**)&csr_in,  g_csr_in);
    cudaGetSymbolAddress((void**)&csr_out, g_csr_out);

    int smemG128 = (128 * 128 + 16 * 256) * (int)sizeof(u64); // 163840
    int smemG64  = (128 * 64  + 16 * 256) * (int)sizeof(u64); // 98304
    cudaFuncSetAttribute(fused_fill_gemm128, cudaFuncAttributeMaxDynamicSharedMemorySize, smemG128);
    cudaFuncSetAttribute(gemm64_kernel,      cudaFuncAttributeMaxDynamicSharedMemorySize, smemG64);

    // ---- CSR build prologue ----
    zero_cnt_kernel<<<(n + 255) / 256, 256>>>(n);
    {
        int threads4 = (E + 3) / 4;
        degree_kernel<<<(threads4 + 255) / 256, 256>>>(ei, E);
    }
    {
        dim3 grid((n + 1023) / 1024, 2);
        offsets_kernel<<<grid, 1024>>>(n);
    }

    // ---- Fused: CSR fill (latency-bound) || GEMM128 (compute-bound) ----
    int fillBlocks = ((E + 3) / 4 + 511) / 512;
    int gemmBlocks = (n + 63) / 64;
    fused_fill_gemm128<<<fillBlocks + gemmBlocks, 512, smemG128>>>(
        ei, E, fillBlocks, x, W1, b1, h0, n);

    // ---- h = relu(agg_in(h0) / (in_deg+1)) ----
    {
        long threads = (long)n * 32;           // NPW=1 for C=128
        agg_kernel<128, true><<<(int)((threads + 511) / 512), 512>>>(h0, off_in, cnt_in, csr_in, h, n);
    }

    // ---- Layer 2 (flipped edges) ----
    gemm64_kernel<<<(n + 63) / 64, 512, smemG64>>>(h, W2, b2, h2, n);
    {
        long threads = ((long)n + 1) / 2 * 32; // NPW=2 for C=64
        agg_kernel<64, false><<<(int)((threads + 511) / 512), 512>>>(h2, off_out, cnt_out, csr_out, out, n);
    }
}

// round 10
// speedup vs baseline: 1.7452x; 1.7452x over previous
#include <cuda_runtime.h>

#define N_NODES 50000
#define MAX_E   900000

// Scratch (device globals — no allocation allowed)
__device__ float g_h0[N_NODES * 128];
__device__ float g_h [N_NODES * 128];
__device__ float g_h2[N_NODES * 64];
__device__ int   g_cnt_in[N_NODES];
__device__ int   g_cnt_out[N_NODES];
__device__ int   g_off_in[N_NODES];
__device__ int   g_off_out[N_NODES];
__device__ int   g_cur_in[N_NODES];
__device__ int   g_cur_out[N_NODES];
__device__ int   g_csr_in[MAX_E];
__device__ int   g_csr_out[MAX_E];
__device__ int   g_base_in;
__device__ int   g_base_out;

typedef unsigned long long u64;

__device__ __forceinline__ u64 pack2(float lo, float hi) {
    u64 r; asm("mov.b64 %0, {%1, %2};" : "=l"(r) : "f"(lo), "f"(hi)); return r;
}
__device__ __forceinline__ void unpack2(u64 v, float& lo, float& hi) {
    asm("mov.b64 {%0, %1}, %2;" : "=f"(lo), "=f"(hi) : "l"(v));
}
__device__ __forceinline__ void fma2(u64& acc, u64 a, u64 b) {
    asm("fma.rn.f32x2 %0, %1, %2, %0;" : "+l"(acc) : "l"(a), "l"(b));
}

__global__ void zero_cnt_kernel(int n) {
    int i = blockIdx.x * blockDim.x + threadIdx.x;
    if (i < n) { g_cnt_in[i] = 0; g_cnt_out[i] = 0; }
    if (i == 0) { g_base_in = 0; g_base_out = 0; }
}

// 4 edges per thread (E % 4 == 0 path): 8 independent atomic chains.
__global__ void degree_kernel4(const int* __restrict__ ei, int E) {
    int i = blockIdx.x * blockDim.x + threadIdx.x;
    if (i * 4 < E) {
        int4 r = ((const int4*)ei)[i];
        int4 c = ((const int4*)(ei + E))[i];
        atomicAdd(&g_cnt_out[r.x], 1); atomicAdd(&g_cnt_out[r.y], 1);
        atomicAdd(&g_cnt_out[r.z], 1); atomicAdd(&g_cnt_out[r.w], 1);
        atomicAdd(&g_cnt_in[c.x], 1); atomicAdd(&g_cnt_in[c.y], 1);
        atomicAdd(&g_cnt_in[c.z], 1); atomicAdd(&g_cnt_in[c.w], 1);
    }
}
__global__ void degree_kernel1(const int* __restrict__ ei, int E) {
    int i = blockIdx.x * blockDim.x + threadIdx.x;
    if (i < E) {
        atomicAdd(&g_cnt_out[ei[i]], 1);
        atomicAdd(&g_cnt_in[ei[E + i]], 1);
    }
}

// Block-local exclusive scan + atomic block base -> CSR segment starts.
__global__ void offsets_kernel(int n) {
    const int* cnt;
    int *off, *cur, *gbase;
    if (blockIdx.y == 0) { cnt = g_cnt_in;  off = g_off_in;  cur = g_cur_in;  gbase = &g_base_in; }
    else                 { cnt = g_cnt_out; off = g_off_out; cur = g_cur_out; gbase = &g_base_out; }

    __shared__ int wsum[32];
    __shared__ int sbase;
    int tid = threadIdx.x, lane = tid & 31, warp = tid >> 5;
    int v = blockIdx.x * blockDim.x + tid;
    int c = (v < n) ? cnt[v] : 0;
    int val = c;
#pragma unroll
    for (int d = 1; d < 32; d <<= 1) {
        int t = __shfl_up_sync(0xffffffffu, val, d);
        if (lane >= d) val += t;
    }
    if (lane == 31) wsum[warp] = val;
    __syncthreads();
    if (warp == 0) {
        int w = wsum[lane];
#pragma unroll
        for (int d = 1; d < 32; d <<= 1) {
            int t = __shfl_up_sync(0xffffffffu, w, d);
            if (lane >= d) w += t;
        }
        wsum[lane] = w;
    }
    __syncthreads();
    int incl = val + (warp ? wsum[warp - 1] : 0);
    if (tid == blockDim.x - 1) sbase = atomicAdd(gbase, incl);
    __syncthreads();
    if (v < n) {
        int o = sbase + incl - c;
        off[v] = o;
        cur[v] = o;
    }
}

__device__ __forceinline__ void fill_one(int r, int c) {
    int p = atomicAdd(&g_cur_in[c], 1);
    g_csr_in[p] = r;
    int q = atomicAdd(&g_cur_out[r], 1);
    g_csr_out[q] = c;
}

__global__ void fill_kernel4(const int* __restrict__ ei, int E) {
    int i = blockIdx.x * blockDim.x + threadIdx.x;
    if (i * 4 < E) {
        int4 r = ((const int4*)ei)[i];
        int4 c = ((const int4*)(ei + E))[i];
        fill_one(r.x, c.x); fill_one(r.y, c.y);
        fill_one(r.z, c.z); fill_one(r.w, c.w);
    }
}
__global__ void fill_kernel1(const int* __restrict__ ei, int E) {
    int e = blockIdx.x * blockDim.x + threadIdx.x;
    if (e < E) fill_one(ei[e], ei[E + e]);
}

// ---------------------------------------------------------------------------
// f32x2 GEMM, column-pair packing (no smem duplication).
// Y = X@W^T + B.  X:[n,128], W:[OUTC,128], B:[OUTC].
// 256 threads = 8 warps; warp = 8 rows; lane = VEC=OUTC/32 adjacent cols
// (VEC/2 f32x2 accumulator pairs per row).
// smem: Wf[k][j] transposed, row padded to OUTC+4 floats (16B-aligned rows,
// conflict-free 16B/lane mainloop reads). Xs[64][128] raw rows (broadcast reads).
// ---------------------------------------------------------------------------
template<int OUTC>
__device__ __forceinline__ void gemm_body(int bid,
                                          const float* __restrict__ X,
                                          const float* __restrict__ W,
                                          const float* __restrict__ B,
                                          float* __restrict__ Y,
                                          int n, float* smF) {
    constexpr int INC  = 128;
    constexpr int VEC  = OUTC / 32;      // cols per lane (4 or 2)
    constexpr int NP   = VEC / 2;        // f32x2 pairs per lane (2 or 1)
    constexpr int OUTP = OUTC + 4;       // padded W row (floats)
    float* Wf = smF;                     // [INC][OUTP]
    float* Xs = smF + INC * OUTP;        // [64][INC]

    int tid = threadIdx.x, lane = tid & 31, warp = tid >> 5;

    // W transpose into smem (gmem coalesced; smem 4-way-conflict stores, one-time)
    for (int i = tid; i < OUTC * INC; i += 256) {
        int j = i / INC, k = i - j * INC;
        Wf[k * OUTP + j] = W[i];
    }

    // X tile: warp loads its 8 rows, one float4 per lane per row (conflict-free)
    int rowBase = bid * 64 + warp * 8;
    float* xw = Xs + warp * 8 * INC;
#pragma unroll
    for (int r = 0; r < 8; r++) {
        int row = rowBase + r;
        if (row < n)
            ((float4*)(xw + r * INC))[lane] =
                ((const float4*)(X + (size_t)row * INC))[lane];
    }
    __syncthreads();

    u64 acc[8][NP];
    {
        u64 binit[NP];
#pragma unroll
        for (int p = 0; p < NP; p++)
            binit[p] = pack2(B[lane * VEC + 2 * p], B[lane * VEC + 2 * p + 1]);
#pragma unroll
        for (int r = 0; r < 8; r++)
#pragma unroll
            for (int p = 0; p < NP; p++) acc[r][p] = binit[p];
    }

    const float* wl = Wf + lane * VEC;
#pragma unroll 2
    for (int k0 = 0; k0 < INC; k0 += 4) {
        float4 xv[8];
#pragma unroll
        for (int r = 0; r < 8; r++)
            xv[r] = *(const float4*)(xw + r * INC + k0);   // warp-broadcast
#pragma unroll
        for (int kk = 0; kk < 4; kk++) {
            u64 w0, w1;
            const float* wb = wl + (k0 + kk) * OUTP;
            if constexpr (NP == 2) {
                ulonglong2 wg = *(const ulonglong2*)wb;
                w0 = wg.x; w1 = wg.y;
            } else {
                w0 = *(const u64*)wb; w1 = 0;
            }
#pragma unroll
            for (int r = 0; r < 8; r++) {
                float xs = ((const float*)&xv[r])[kk];
                u64 xx = pack2(xs, xs);
                fma2(acc[r][0], xx, w0);
                if constexpr (NP == 2) fma2(acc[r][1], xx, w1);
            }
        }
    }

#pragma unroll
    for (int r = 0; r < 8; r++) {
        int row = rowBase + r;
        if (row < n) {
            float res[VEC];
#pragma unroll
            for (int p = 0; p < NP; p++)
                unpack2(acc[r][p], res[2 * p], res[2 * p + 1]);
            if constexpr (VEC == 4) {
                float4 o = make_float4(res[0], res[1], res[2], res[3]);
                ((float4*)(Y + (size_t)row * OUTC))[lane] = o;
            } else {
                float2 o = make_float2(res[0], res[1]);
                ((float2*)(Y + (size_t)row * OUTC))[lane] = o;
            }
        }
    }
}

__global__ void gemm128_kernel(const float* __restrict__ X, const float* __restrict__ W,
                               const float* __restrict__ B, float* __restrict__ Y, int n) {
    extern __shared__ float smF[];
    gemm_body<128>(blockIdx.x, X, W, B, Y, n, smF);
}
__global__ void gemm64_kernel(const float* __restrict__ X, const float* __restrict__ W,
                              const float* __restrict__ B, float* __restrict__ Y, int n) {
    extern __shared__ float smF[];
    gemm_body<64>(blockIdx.x, X, W, B, Y, n, smF);
}

// CSR gather-aggregation, fused with normalization (and optional ReLU).
template<int C, bool RELU>
__global__ void agg_kernel(const float* __restrict__ src,
                           const int* __restrict__ off,
                           const int* __restrict__ cnt,
                           const int* __restrict__ csr,
                           float* __restrict__ dst, int n) {
    constexpr int LPE = C / 4;
    constexpr int NPW = 32 / LPE;
    int t = blockIdx.x * blockDim.x + threadIdx.x;
    int warp = t >> 5, lane = t & 31;
    int sub = lane / LPE, li = lane - sub * LPE;
    int v = warp * NPW + sub;
    if (v >= n) return;

    int beg = off[v];
    int deg = cnt[v];
    int end = beg + deg;

    float4 acc = ((const float4*)(src + (size_t)v * C))[li];  // self loop
    int e = beg;
    for (; e + 4 <= end; e += 4) {
        int s0 = csr[e], s1 = csr[e + 1], s2 = csr[e + 2], s3 = csr[e + 3];
        float4 a = ((const float4*)(src + (size_t)s0 * C))[li];
        float4 b = ((const float4*)(src + (size_t)s1 * C))[li];
        float4 c = ((const float4*)(src + (size_t)s2 * C))[li];
        float4 d = ((const float4*)(src + (size_t)s3 * C))[li];
        acc.x += (a.x + b.x) + (c.x + d.x);
        acc.y += (a.y + b.y) + (c.y + d.y);
        acc.z += (a.z + b.z) + (c.z + d.z);
        acc.w += (a.w + b.w) + (c.w + d.w);
    }
    for (; e < end; e++) {
        int s = csr[e];
        float4 a = ((const float4*)(src + (size_t)s * C))[li];
        acc.x += a.x; acc.y += a.y; acc.z += a.z; acc.w += a.w;
    }

    float inv = 1.0f / (float)(deg + 1);
    acc.x *= inv; acc.y *= inv; acc.z *= inv; acc.w *= inv;
    if (RELU) {
        acc.x = fmaxf(acc.x, 0.0f); acc.y = fmaxf(acc.y, 0.0f);
        acc.z = fmaxf(acc.z, 0.0f); acc.w = fmaxf(acc.w, 0.0f);
    }
    ((float4*)(dst + (size_t)v * C))[li] = acc;
}

extern "C" void kernel_launch(void* const* d_in, const int* in_sizes, int n_in,
                              void* d_out, int out_size) {
    const float* x  = (const float*)d_in[0];
    const int*   ei = (const int*)d_in[1];
    const float* W1 = (const float*)d_in[2];
    const float* b1 = (const float*)d_in[3];
    const float* W2 = (const float*)d_in[4];
    const float* b2 = (const float*)d_in[5];
    float* out = (float*)d_out;

    int n = in_sizes[0] / 128;
    int E = in_sizes[1] / 2;

    float *h0, *h, *h2;
    int *cnt_in, *cnt_out, *off_in, *off_out, *csr_in, *csr_out;
    cudaGetSymbolAddress((void**)&h0, g_h0);
    cudaGetSymbolAddress((void**)&h,  g_h);
    cudaGetSymbolAddress((void**)&h2, g_h2);
    cudaGetSymbolAddress((void**)&cnt_in,  g_cnt_in);
    cudaGetSymbolAddress((void**)&cnt_out, g_cnt_out);
    cudaGetSymbolAddress((void**)&off_in,  g_off_in);
    cudaGetSymbolAddress((void**)&off_out, g_off_out);
    cudaGetSymbolAddress((void**)&csr_in,  g_csr_in);
    cudaGetSymbolAddress((void**)&csr_out, g_csr_out);

    int smem1 = (128 * (128 + 4) + 64 * 128) * (int)sizeof(float); // 100352
    int smem2 = (128 * (64 + 4)  + 64 * 128) * (int)sizeof(float); // 67584
    cudaFuncSetAttribute(gemm128_kernel, cudaFuncAttributeMaxDynamicSharedMemorySize, smem1);
    cudaFuncSetAttribute(gemm64_kernel,  cudaFuncAttributeMaxDynamicSharedMemorySize, smem2);

    // ---- CSR build ----
    zero_cnt_kernel<<<(n + 255) / 256, 256>>>(n);
    if ((E & 3) == 0) {
        int t4 = E / 4;
        degree_kernel4<<<(t4 + 255) / 256, 256>>>(ei, E);
    } else {
        degree_kernel1<<<(E + 255) / 256, 256>>>(ei, E);
    }
    {
        dim3 grid((n + 1023) / 1024, 2);
        offsets_kernel<<<grid, 1024>>>(n);
    }
    if ((E & 3) == 0) {
        int t4 = E / 4;
        fill_kernel4<<<(t4 + 255) / 256, 256>>>(ei, E);
    } else {
        fill_kernel1<<<(E + 255) / 256, 256>>>(ei, E);
    }

    // ---- Layer 1: h0 = x@W1^T + b1 ; h = relu(agg_in(h0) / (in_deg+1)) ----
    gemm128_kernel<<<(n + 63) / 64, 256, smem1>>>(x, W1, b1, h0, n);
    {
        long threads = (long)n * 32;           // NPW=1 for C=128
        agg_kernel<128, true><<<(int)((threads + 511) / 512), 512>>>(h0, off_in, cnt_in, csr_in, h, n);
    }

    // ---- Layer 2 (flipped edges) ----
    gemm64_kernel<<<(n + 63) / 64, 256, smem2>>>(h, W2, b2, h2, n);
    {
        long threads = ((long)n + 1) / 2 * 32; // NPW=2 for C=64
        agg_kernel<64, false><<<(int)((threads + 511) / 512), 512>>>(h2, off_out, cnt_out, csr_out, out, n);
    }
}